// round 2
// baseline (speedup 1.0000x reference)
#include <cuda_runtime.h>

#define BB 4
#define CCH 64
#define FF 256
#define TT 256
#define TCC 64
#define DD 16
#define YY 320            // TCC + TT
#define FCH 8             // f-chunks for t-softmax stats
#define OUT0 16777216     // B*C*F*T, offset of new_cache in d_out

// -------- device scratch (static allocation only, per harness rules) --------
__device__ float g_fqkv[BB*48*FF*TT];   // [b][o<48][f][t]   o: 0-15 qf, 16-31 kf, 32-47 v
__device__ float g_qt  [BB*DD*FF*TT];   // [b][c][f][t]
__device__ float g_ktf [BB*DD*FF*YY];   // [b][c][f][y]  (y<64: k_cache, y>=64: kt)
__device__ float g_fo  [BB*DD*FF*YY];   // [b][c][f][y]  (y<64: v_cache, y>=64: f-attn out)
__device__ float g_zp  [BB*FCH*YY*TT];  // partial sum_f exp(s)
__device__ float g_zinv[BB*YY*TT];      // 1 / sum_f exp(s), layout [b][y][t]

// ---------------------------------------------------------------------------
// K1: fused 1x1 conv + BN + PReLU for fqkv (48ch) and tqk (32ch)
// grid (f=256, b=4), 256 threads over t. Coalesced reads & writes.
// ---------------------------------------------------------------------------
__global__ void __launch_bounds__(256)
k_conv(const float* __restrict__ inp,
       const float* __restrict__ fw, const float* __restrict__ fg,
       const float* __restrict__ fb, const float* __restrict__ fm,
       const float* __restrict__ fv, const float* __restrict__ fa,
       const float* __restrict__ tw, const float* __restrict__ tg,
       const float* __restrict__ tb, const float* __restrict__ tm,
       const float* __restrict__ tv, const float* __restrict__ ta)
{
    __shared__ float w_s[80*64];
    __shared__ float sc_s[80], sh_s[80], al_s[80];
    int f = blockIdx.x, b = blockIdx.y, t = threadIdx.x;

    for (int i = t; i < 48*64; i += 256) w_s[i]         = fw[i];
    for (int i = t; i < 32*64; i += 256) w_s[48*64 + i] = tw[i];
    if (t < 48) {
        float s = fg[t] * rsqrtf(fv[t] + 1e-5f);
        sc_s[t] = s; sh_s[t] = fb[t] - fm[t]*s; al_s[t] = fa[t];
    } else if (t < 80) {
        int o = t - 48;
        float s = tg[o] * rsqrtf(tv[o] + 1e-5f);
        sc_s[t] = s; sh_s[t] = tb[o] - tm[o]*s; al_s[t] = ta[o];
    }
    __syncthreads();

    float x[64];
    #pragma unroll
    for (int c = 0; c < 64; c++) x[c] = inp[((b*64 + c)*256 + f)*256 + t];

    #pragma unroll 2
    for (int o = 0; o < 80; o++) {
        float acc = 0.f;
        #pragma unroll
        for (int c = 0; c < 64; c++) acc += w_s[o*64 + c] * x[c];
        acc = acc * sc_s[o] + sh_s[o];
        acc = (acc >= 0.f) ? acc : al_s[o] * acc;
        if (o < 48)      g_fqkv[((b*48 + o)*256 + f)*256 + t] = acc;
        else if (o < 64) g_qt  [((b*16 + (o-48))*256 + f)*256 + t] = acc;
        else             g_ktf [((b*16 + (o-64))*256 + f)*320 + 64 + t] = acc;
    }
}

// ---------------------------------------------------------------------------
// K1c: scatter cache into the 320-wide k/v buffers (y in [0,64))
// ---------------------------------------------------------------------------
__global__ void __launch_bounds__(256)
k_cachecopy(const float* __restrict__ cache)
{
    int i = blockIdx.x*256 + threadIdx.x;          // BB*DD*FF*TCC = 1,048,576
    if (i >= BB*DD*FF*TCC) return;
    int t = i % TCC;
    int f = (i / TCC) % FF;
    int c = (i / (TCC*FF)) % DD;
    int b =  i / (TCC*FF*DD);
    g_ktf[((b*16 + c)*256 + f)*320 + t] = cache[((b*32 + c     )*FF + f)*TCC + t];
    g_fo [((b*16 + c)*256 + f)*320 + t] = cache[((b*32 + 16 + c)*FF + f)*TCC + t];
}

// ---------------------------------------------------------------------------
// K2: frequency attention. One block per (b,t); thread = f row.
// s[f,y] = 0.25 * sum_c qf[c,f]*kf[c,y]; softmax over y (no max-sub: exp safe);
// out[c,f] = sum_y p*v[c,y] -> g_fo[..][64+t]
// ---------------------------------------------------------------------------
__global__ void __launch_bounds__(256)
k_fattn()
{
    __shared__ float k_s[16][256];
    __shared__ float v_s[16][256];
    int t = blockIdx.x, b = blockIdx.y, f = threadIdx.x;
    const float* base = g_fqkv + (size_t)b*48*256*256;

    #pragma unroll
    for (int c = 0; c < 16; c++) {
        k_s[c][f] = base[((16 + c)*256 + f)*256 + t];
        v_s[c][f] = base[((32 + c)*256 + f)*256 + t];
    }
    float q[16];
    #pragma unroll
    for (int c = 0; c < 16; c++) q[c] = base[(c*256 + f)*256 + t];
    __syncthreads();

    float l = 0.f, acc[16];
    #pragma unroll
    for (int c = 0; c < 16; c++) acc[c] = 0.f;

    for (int y = 0; y < 256; y++) {
        float s = 0.f;
        #pragma unroll
        for (int c = 0; c < 16; c++) s += q[c] * k_s[c][y];
        float e = __expf(0.25f * s);
        l += e;
        #pragma unroll
        for (int c = 0; c < 16; c++) acc[c] += e * v_s[c][y];
    }
    float rl = 1.f / l;
    #pragma unroll
    for (int c = 0; c < 16; c++)
        g_fo[((b*16 + c)*256 + f)*320 + 64 + t] = acc[c] * rl;
}

// ---------------------------------------------------------------------------
// K3: t-attention softmax denominators (softmax is over f!).
// grid (tt=8, fc=8, b=4); each block: 32 t's x 320 y's, partial over 32 f's.
// ---------------------------------------------------------------------------
__global__ void __launch_bounds__(256)
k_tstats()
{
    __shared__ float q_s[16][32];
    __shared__ float k_s[16][320];
    int t0 = blockIdx.x * 32, f0 = blockIdx.y * 32, b = blockIdx.z;
    int tid = threadIdx.x;

    float z[40];
    #pragma unroll
    for (int j = 0; j < 40; j++) z[j] = 0.f;

    for (int fi = 0; fi < 32; fi++) {
        int f = f0 + fi;
        __syncthreads();
        for (int i = tid; i < 16*32; i += 256) {
            int c = i / 32, tl = i % 32;
            q_s[c][tl] = g_qt[((b*16 + c)*256 + f)*256 + t0 + tl];
        }
        for (int i = tid; i < 16*320; i += 256) {
            int c = i / 320, y = i % 320;
            k_s[c][y] = g_ktf[((b*16 + c)*256 + f)*320 + y];
        }
        __syncthreads();
        #pragma unroll
        for (int j = 0; j < 40; j++) {
            int e = tid + 256*j;
            int y = e >> 5, tl = e & 31;
            float s = 0.f;
            #pragma unroll
            for (int c = 0; c < 16; c++) s += q_s[c][tl] * k_s[c][y];
            z[j] += __expf(0.25f * s);
        }
    }
    #pragma unroll
    for (int j = 0; j < 40; j++) {
        int e = tid + 256*j;
        int y = e >> 5, tl = e & 31;
        g_zp[((b*8 + blockIdx.y)*320 + y)*256 + t0 + tl] = z[j];
    }
}

// ---------------------------------------------------------------------------
// K3b: reduce 8 partials -> reciprocal of denominator
// ---------------------------------------------------------------------------
__global__ void __launch_bounds__(256)
k_zreduce()
{
    int i = blockIdx.x*256 + threadIdx.x;          // BB*YY*TT = 327,680
    if (i >= BB*YY*TT) return;
    int t = i % 256;
    int y = (i / 256) % 320;
    int b =  i / (256*320);
    float s = 0.f;
    #pragma unroll
    for (int fc = 0; fc < 8; fc++) s += g_zp[((b*8 + fc)*320 + y)*256 + t];
    g_zinv[i] = 1.f / s;
}

// ---------------------------------------------------------------------------
// K4: t-attention output, fused with proj conv + BN + PReLU + residual.
// grid (f=256, b=4), 256 threads over t.
// t_out[c,f,t] = sum_y exp(s)*zinv[t,y] * f_out[c,f,y]; then 64-ch proj.
// ---------------------------------------------------------------------------
__global__ void __launch_bounds__(256)
k_tattn_proj(const float* __restrict__ inp,
             const float* __restrict__ pw, const float* __restrict__ pg,
             const float* __restrict__ pb, const float* __restrict__ pm,
             const float* __restrict__ pv, const float* __restrict__ pa,
             float* __restrict__ out)
{
    __shared__ float k_s[16][320];
    __shared__ float fo_s[16][320];
    __shared__ float w_s[64*16];
    __shared__ float psc[64], psh[64], pal[64];
    int f = blockIdx.x, b = blockIdx.y, t = threadIdx.x;

    for (int i = t; i < 16*320; i += 256) {
        int c = i / 320, y = i % 320;
        k_s [c][y] = g_ktf[((b*16 + c)*256 + f)*320 + y];
        fo_s[c][y] = g_fo [((b*16 + c)*256 + f)*320 + y];
    }
    for (int i = t; i < 64*16; i += 256) w_s[i] = pw[i];
    if (t < 64) {
        float s = pg[t] * rsqrtf(pv[t] + 1e-5f);
        psc[t] = s; psh[t] = pb[t] - pm[t]*s; pal[t] = pa[t];
    }
    float q[16];
    #pragma unroll
    for (int c = 0; c < 16; c++) q[c] = g_qt[((b*16 + c)*256 + f)*256 + t];
    __syncthreads();

    float acc[16];
    #pragma unroll
    for (int c = 0; c < 16; c++) acc[c] = 0.f;

    const float* zin = g_zinv + (size_t)b*320*256 + t;
    for (int y = 0; y < 320; y++) {
        float s = 0.f;
        #pragma unroll
        for (int c = 0; c < 16; c++) s += q[c] * k_s[c][y];
        float p = __expf(0.25f * s) * zin[y*256];
        #pragma unroll
        for (int c = 0; c < 16; c++) acc[c] += p * fo_s[c][y];
    }

    #pragma unroll 2
    for (int o = 0; o < 64; o++) {
        float r = 0.f;
        #pragma unroll
        for (int c = 0; c < 16; c++) r += w_s[o*16 + c] * acc[c];
        r = r * psc[o] + psh[o];
        r = (r >= 0.f) ? r : pal[o] * r;
        r += inp[((b*64 + o)*256 + f)*256 + t];
        out[((b*64 + o)*256 + f)*256 + t] = r;
    }
}

// ---------------------------------------------------------------------------
// K5: emit new_cache = concat(kt[...,1:], f_out[...,1:]) at d_out + OUT0
// total elements: BB*32*FF*319 = 10,452,992  (fits in 32-bit int)
// ---------------------------------------------------------------------------
__global__ void __launch_bounds__(256)
k_cacheout(float* __restrict__ out)
{
    int i = blockIdx.x*256 + threadIdx.x;
    if (i >= BB*32*FF*319) return;
    int j  = i % 319;
    int r  = i / 319;
    int f  = r % 256; r /= 256;
    int cc = r % 32;
    int b  = r / 32;
    float val;
    if (cc < 16) val = g_ktf[((b*16 + cc     )*256 + f)*320 + j + 1];
    else         val = g_fo [((b*16 + (cc-16))*256 + f)*320 + j + 1];
    out[OUT0 + i] = val;
}

// ---------------------------------------------------------------------------
extern "C" void kernel_launch(void* const* d_in, const int* in_sizes, int n_in,
                              void* d_out, int out_size)
{
    const float* inp    = (const float*)d_in[0];
    const float* cache  = (const float*)d_in[1];
    const float* fqkv_w = (const float*)d_in[2];
    const float* fqkv_g = (const float*)d_in[3];
    const float* fqkv_b = (const float*)d_in[4];
    const float* fqkv_m = (const float*)d_in[5];
    const float* fqkv_v = (const float*)d_in[6];
    const float* fqkv_a = (const float*)d_in[7];
    const float* tqk_w  = (const float*)d_in[8];
    const float* tqk_g  = (const float*)d_in[9];
    const float* tqk_b  = (const float*)d_in[10];
    const float* tqk_m  = (const float*)d_in[11];
    const float* tqk_v  = (const float*)d_in[12];
    const float* tqk_a  = (const float*)d_in[13];
    const float* proj_w = (const float*)d_in[14];
    const float* proj_g = (const float*)d_in[15];
    const float* proj_b = (const float*)d_in[16];
    const float* proj_m = (const float*)d_in[17];
    const float* proj_v = (const float*)d_in[18];
    const float* proj_a = (const float*)d_in[19];
    float* out = (float*)d_out;

    dim3 gconv(256, 4);
    k_conv<<<gconv, 256>>>(inp, fqkv_w, fqkv_g, fqkv_b, fqkv_m, fqkv_v, fqkv_a,
                                tqk_w,  tqk_g,  tqk_b,  tqk_m,  tqk_v,  tqk_a);
    k_cachecopy<<<(BB*DD*FF*TCC + 255)/256, 256>>>(cache);

    dim3 gf(256, 4);
    k_fattn<<<gf, 256>>>();

    dim3 gs(8, 8, 4);
    k_tstats<<<gs, 256>>>();
    k_zreduce<<<(BB*YY*TT + 255)/256, 256>>>();

    dim3 gt(256, 4);
    k_tattn_proj<<<gt, 256>>>(inp, proj_w, proj_g, proj_b, proj_m, proj_v, proj_a, out);

    k_cacheout<<<(BB*32*FF*319 + 255)/256, 256>>>(out);
}

// round 3
// speedup vs baseline: 1.5265x; 1.5265x over previous
#include <cuda_runtime.h>

#define BB 4
#define CCH 64
#define FF 256
#define TT 256
#define TCC 64
#define DD 16
#define YY 320            // TCC + TT
#define OUT0 16777216     // B*C*F*T, offset of new_cache in d_out

// -------- device scratch (static allocation only, per harness rules) --------
__device__ float g_fqkv [BB*48*FF*TT];   // [b][o][f][t]   o: 0-15 qf, 16-31 kf, 32-47 v
__device__ float g_fqkvT[BB*48*TT*FF];   // [b][o][t][f]
__device__ float g_qt  [BB*DD*FF*TT];    // [b][c][f][t]
__device__ float g_ktf [BB*DD*FF*YY];    // [b][c][f][y]  (y<64: k_cache, y>=64: kt)
__device__ float g_fo  [BB*DD*FF*YY];    // [b][c][f][y]  (y<64: v_cache, y>=64: f-attn out)
__device__ float g_foT [BB*DD*TT*FF];    // [b][c][t][f]  f-attn raw out
__device__ float g_e   [(size_t)BB*FF*YY*TT]; // exp(score/4), [b][f][y][t]  (335MB)
__device__ float g_zinv[BB*YY*TT];       // 1 / sum_f e, layout [b][y][t]

// ---------------------------------------------------------------------------
// K1: fused 1x1 conv + BN + PReLU for fqkv (48ch) and tqk (32ch)
// grid (f=256, b=4), 256 threads over t.
// ---------------------------------------------------------------------------
__global__ void __launch_bounds__(256)
k_conv(const float* __restrict__ inp,
       const float* __restrict__ fw, const float* __restrict__ fg,
       const float* __restrict__ fb, const float* __restrict__ fm,
       const float* __restrict__ fv, const float* __restrict__ fa,
       const float* __restrict__ tw, const float* __restrict__ tg,
       const float* __restrict__ tb, const float* __restrict__ tm,
       const float* __restrict__ tv, const float* __restrict__ ta)
{
    __shared__ float w_s[80*64];
    __shared__ float sc_s[80], sh_s[80], al_s[80];
    int f = blockIdx.x, b = blockIdx.y, t = threadIdx.x;

    for (int i = t; i < 48*64; i += 256) w_s[i]         = fw[i];
    for (int i = t; i < 32*64; i += 256) w_s[48*64 + i] = tw[i];
    if (t < 48) {
        float s = fg[t] * rsqrtf(fv[t] + 1e-5f);
        sc_s[t] = s; sh_s[t] = fb[t] - fm[t]*s; al_s[t] = fa[t];
    } else if (t < 80) {
        int o = t - 48;
        float s = tg[o] * rsqrtf(tv[o] + 1e-5f);
        sc_s[t] = s; sh_s[t] = tb[o] - tm[o]*s; al_s[t] = ta[o];
    }
    __syncthreads();

    float x[64];
    #pragma unroll
    for (int c = 0; c < 64; c++) x[c] = inp[((b*64 + c)*256 + f)*256 + t];

    #pragma unroll 2
    for (int o = 0; o < 80; o++) {
        const float4* w4 = (const float4*)&w_s[o*64];
        float acc = 0.f;
        #pragma unroll
        for (int c4 = 0; c4 < 16; c4++) {
            float4 w = w4[c4];
            acc += w.x*x[c4*4+0] + w.y*x[c4*4+1] + w.z*x[c4*4+2] + w.w*x[c4*4+3];
        }
        acc = acc * sc_s[o] + sh_s[o];
        acc = (acc >= 0.f) ? acc : al_s[o] * acc;
        if (o < 48)      g_fqkv[((b*48 + o)*256 + f)*256 + t] = acc;
        else if (o < 64) g_qt  [((b*16 + (o-48))*256 + f)*256 + t] = acc;
        else             g_ktf [((b*16 + (o-64))*256 + f)*320 + 64 + t] = acc;
    }
}

// ---------------------------------------------------------------------------
// T1: transpose qf/kf/v: [ch][f][t] -> [ch][t][f], 32x32 tiles. grid (8,8,192)
// ---------------------------------------------------------------------------
__global__ void __launch_bounds__(256)
k_trans1()
{
    __shared__ float tile[32][33];
    int f0 = blockIdx.x*32, t0 = blockIdx.y*32, ch = blockIdx.z;
    const float* src = g_fqkv  + (size_t)ch*65536;
    float*       dst = g_fqkvT + (size_t)ch*65536;
    int tx = threadIdx.x & 31, ty = threadIdx.x >> 5;
    #pragma unroll
    for (int k = 0; k < 4; k++)
        tile[ty+8*k][tx] = src[(f0+ty+8*k)*256 + t0+tx];
    __syncthreads();
    #pragma unroll
    for (int k = 0; k < 4; k++)
        dst[(t0+ty+8*k)*256 + f0+tx] = tile[tx][ty+8*k];
}

// ---------------------------------------------------------------------------
// K1c: scatter cache into the 320-wide k/v buffers (y in [0,64))
// ---------------------------------------------------------------------------
__global__ void __launch_bounds__(256)
k_cachecopy(const float* __restrict__ cache)
{
    int i = blockIdx.x*256 + threadIdx.x;          // BB*DD*FF*TCC = 1,048,576
    if (i >= BB*DD*FF*TCC) return;
    int t = i % TCC;
    int f = (i / TCC) % FF;
    int c = (i / (TCC*FF)) % DD;
    int b =  i / (TCC*FF*DD);
    g_ktf[((b*16 + c)*256 + f)*320 + t] = cache[((b*32 + c     )*FF + f)*TCC + t];
    g_fo [((b*16 + c)*256 + f)*320 + t] = cache[((b*32 + 16 + c)*FF + f)*TCC + t];
}

// ---------------------------------------------------------------------------
// K2: frequency attention. One block per (b,t); thread = f row.
// k/v staged as [y][c] rows (20-float pitch) -> 8x LDS.128 + 32 FFMA per y.
// Writes g_foT[c][t][f] (coalesced in f).
// ---------------------------------------------------------------------------
__global__ void __launch_bounds__(256)
k_fattn()
{
    __shared__ float k_s[256][20];
    __shared__ float v_s[256][20];
    int t = blockIdx.x, b = blockIdx.y, fth = threadIdx.x;
    const float* baseT = g_fqkvT + (size_t)b*48*65536;

    for (int i = fth; i < 16*256; i += 256) {
        int c = i >> 8, y = i & 255;
        k_s[y][c] = baseT[((16 + c)*256 + t)*256 + y];
        v_s[y][c] = baseT[((32 + c)*256 + t)*256 + y];
    }
    float q[16];
    #pragma unroll
    for (int c = 0; c < 16; c++) q[c] = baseT[(c*256 + t)*256 + fth];
    __syncthreads();

    float l = 0.f, acc[16];
    #pragma unroll
    for (int c = 0; c < 16; c++) acc[c] = 0.f;

    for (int y = 0; y < 256; y++) {
        const float4* kr = (const float4*)&k_s[y][0];
        float4 k0 = kr[0], k1 = kr[1], k2 = kr[2], k3 = kr[3];
        float s = q[0]*k0.x + q[1]*k0.y + q[2]*k0.z + q[3]*k0.w
                + q[4]*k1.x + q[5]*k1.y + q[6]*k1.z + q[7]*k1.w
                + q[8]*k2.x + q[9]*k2.y + q[10]*k2.z + q[11]*k2.w
                + q[12]*k3.x + q[13]*k3.y + q[14]*k3.z + q[15]*k3.w;
        float e = __expf(0.25f * s);
        l += e;
        const float4* vr = (const float4*)&v_s[y][0];
        float4 v0 = vr[0], v1 = vr[1], v2 = vr[2], v3 = vr[3];
        acc[0]  += e*v0.x; acc[1]  += e*v0.y; acc[2]  += e*v0.z; acc[3]  += e*v0.w;
        acc[4]  += e*v1.x; acc[5]  += e*v1.y; acc[6]  += e*v1.z; acc[7]  += e*v1.w;
        acc[8]  += e*v2.x; acc[9]  += e*v2.y; acc[10] += e*v2.z; acc[11] += e*v2.w;
        acc[12] += e*v3.x; acc[13] += e*v3.y; acc[14] += e*v3.z; acc[15] += e*v3.w;
    }
    float rl = 1.f / l;
    #pragma unroll
    for (int c = 0; c < 16; c++)
        g_foT[((b*16 + c)*256 + t)*256 + fth] = acc[c] * rl;
}

// ---------------------------------------------------------------------------
// T2: f-attn out [c][t][f] -> g_fo[c][f][64+t]. grid (8,8,64)
// ---------------------------------------------------------------------------
__global__ void __launch_bounds__(256)
k_trans2()
{
    __shared__ float tile[32][33];
    int t0 = blockIdx.x*32, f0 = blockIdx.y*32, ch = blockIdx.z;  // ch = b*16+c
    const float* src = g_foT + (size_t)ch*65536;
    float*       dst = g_fo  + (size_t)ch*256*320;
    int tx = threadIdx.x & 31, ty = threadIdx.x >> 5;
    #pragma unroll
    for (int k = 0; k < 4; k++)
        tile[ty+8*k][tx] = src[(t0+ty+8*k)*256 + f0+tx];   // rows t, cols f (coalesced)
    __syncthreads();
    #pragma unroll
    for (int k = 0; k < 4; k++)
        dst[(f0+ty+8*k)*320 + 64 + t0+tx] = tile[tx][ty+8*k]; // coalesced in t
}

// ---------------------------------------------------------------------------
// A: t-attention scores. grid (f=256, b=4), 256 thr (tx<32 over t, ty<8 over y).
// Per-thread 8x8 tile; e = exp(s/4) stored to g_e[b][f][y][t].
// ---------------------------------------------------------------------------
__global__ void __launch_bounds__(256)
k_tscore()
{
    __shared__ float Qs[16][256];
    __shared__ float Ks[16][320];
    int f = blockIdx.x, b = blockIdx.y;
    int tid = threadIdx.x;
    int tx = tid & 31, ty = tid >> 5;

    for (int i = tid; i < 16*256; i += 256) {
        int c = i >> 8, t = i & 255;
        Qs[c][t] = g_qt[((b*16 + c)*256 + f)*256 + t];
    }
    for (int i = tid; i < 16*320; i += 256) {
        int c = i / 320, y = i - c*320;
        Ks[c][y] = g_ktf[((b*16 + c)*256 + f)*320 + y];
    }
    __syncthreads();

    float* ebase = g_e + (size_t)(b*256 + f)*320*256;

    #pragma unroll 1
    for (int yc = 0; yc < 320; yc += 64) {
        float acc[8][8];
        #pragma unroll
        for (int i = 0; i < 8; i++)
            #pragma unroll
            for (int m = 0; m < 8; m++) acc[i][m] = 0.f;

        int y0 = yc + ty*8;
        #pragma unroll
        for (int c = 0; c < 16; c++) {
            float qv[8];
            #pragma unroll
            for (int i = 0; i < 8; i++) qv[i] = Qs[c][tx + 32*i];
            float4 ka = *(const float4*)&Ks[c][y0];
            float4 kb = *(const float4*)&Ks[c][y0+4];
            float kv[8] = {ka.x, ka.y, ka.z, ka.w, kb.x, kb.y, kb.z, kb.w};
            #pragma unroll
            for (int i = 0; i < 8; i++)
                #pragma unroll
                for (int m = 0; m < 8; m++) acc[i][m] += qv[i]*kv[m];
        }
        #pragma unroll
        for (int m = 0; m < 8; m++) {
            float* row = ebase + (size_t)(y0 + m)*256;
            #pragma unroll
            for (int i = 0; i < 8; i++)
                row[tx + 32*i] = __expf(0.25f * acc[i][m]);
        }
    }
}

// ---------------------------------------------------------------------------
// B: Z[b][y][t] = sum_f e[b][f][y][t]; store reciprocal. grid (320, 4), 256 thr.
// ---------------------------------------------------------------------------
__global__ void __launch_bounds__(256)
k_zred()
{
    int y = blockIdx.x, b = blockIdx.y, t = threadIdx.x;
    const float* p = g_e + ((size_t)b*256*320 + y)*256 + t;
    float s = 0.f;
    #pragma unroll 8
    for (int f = 0; f < 256; f++) s += p[(size_t)f*320*256];
    g_zinv[(b*320 + y)*256 + t] = 1.f / s;
}

// ---------------------------------------------------------------------------
// C: t_out[c,t] = sum_y e[y][t]*zinv[y][t]*fo[c][y]; fused proj+BN+PReLU+res.
// grid (f=256, b=4), 256 threads. P chunked 16 y's; thread tile 4t x 4c.
// ---------------------------------------------------------------------------
__global__ void __launch_bounds__(256)
k_tout_proj(const float* __restrict__ inp,
            const float* __restrict__ pw, const float* __restrict__ pg,
            const float* __restrict__ pb, const float* __restrict__ pm,
            const float* __restrict__ pv, const float* __restrict__ pa,
            float* __restrict__ out)
{
    __shared__ float fo_s[16][321];
    __shared__ float pool[256*18];          // P_s (16x256) then T_s (256x18)
    __shared__ float w_s[64*16];
    __shared__ float psc[64], psh[64], pal[64];
    int f = blockIdx.x, b = blockIdx.y, tid = threadIdx.x;

    for (int i = tid; i < 16*320; i += 256) {
        int c = i / 320, y = i - c*320;
        fo_s[c][y] = g_fo[((b*16 + c)*256 + f)*320 + y];
    }
    for (int i = tid; i < 64*16; i += 256) w_s[i] = pw[i];
    if (tid < 64) {
        float s = pg[tid] * rsqrtf(pv[tid] + 1e-5f);
        psc[tid] = s; psh[tid] = pb[tid] - pm[tid]*s; pal[tid] = pa[tid];
    }

    int tg = tid >> 2, cg = tid & 3;        // t base tg*4, c base cg*4
    float acc[4][4];
    #pragma unroll
    for (int j = 0; j < 4; j++)
        #pragma unroll
        for (int k = 0; k < 4; k++) acc[j][k] = 0.f;

    const float* ebase = g_e + (size_t)(b*256 + f)*320*256;
    const float* zbase = g_zinv + b*320*256;

    for (int y0 = 0; y0 < 320; y0 += 16) {
        __syncthreads();
        #pragma unroll
        for (int r = 0; r < 16; r++) {
            int i = tid + 256*r;            // 4096 elems, 16 per thread
            int yy = i >> 8, t = i & 255;
            int y = y0 + yy;
            pool[i] = ebase[(size_t)y*256 + t] * zbase[y*256 + t];
        }
        __syncthreads();
        #pragma unroll
        for (int yy = 0; yy < 16; yy++) {
            float4 p4 = *(const float4*)&pool[yy*256 + tg*4];
            int y = y0 + yy;
            float f0 = fo_s[cg*4+0][y];
            float f1 = fo_s[cg*4+1][y];
            float f2 = fo_s[cg*4+2][y];
            float f3 = fo_s[cg*4+3][y];
            acc[0][0] += p4.x*f0; acc[0][1] += p4.x*f1; acc[0][2] += p4.x*f2; acc[0][3] += p4.x*f3;
            acc[1][0] += p4.y*f0; acc[1][1] += p4.y*f1; acc[1][2] += p4.y*f2; acc[1][3] += p4.y*f3;
            acc[2][0] += p4.z*f0; acc[2][1] += p4.z*f1; acc[2][2] += p4.z*f2; acc[2][3] += p4.z*f3;
            acc[3][0] += p4.w*f0; acc[3][1] += p4.w*f1; acc[3][2] += p4.w*f2; acc[3][3] += p4.w*f3;
        }
    }

    __syncthreads();
    #pragma unroll
    for (int j = 0; j < 4; j++)
        #pragma unroll
        for (int k = 0; k < 4; k++)
            pool[(tg*4 + j)*18 + cg*4 + k] = acc[j][k];   // T_s view, pitch 18
    __syncthreads();

    float tv[16];
    #pragma unroll
    for (int c = 0; c < 16; c++) tv[c] = pool[tid*18 + c];

    #pragma unroll 2
    for (int o = 0; o < 64; o++) {
        const float4* w4 = (const float4*)&w_s[o*16];
        float4 w0 = w4[0], w1 = w4[1], w2 = w4[2], w3 = w4[3];
        float r = w0.x*tv[0] + w0.y*tv[1] + w0.z*tv[2] + w0.w*tv[3]
                + w1.x*tv[4] + w1.y*tv[5] + w1.z*tv[6] + w1.w*tv[7]
                + w2.x*tv[8] + w2.y*tv[9] + w2.z*tv[10] + w2.w*tv[11]
                + w3.x*tv[12] + w3.y*tv[13] + w3.z*tv[14] + w3.w*tv[15];
        r = r * psc[o] + psh[o];
        r = (r >= 0.f) ? r : pal[o] * r;
        r += inp[((b*64 + o)*256 + f)*256 + tid];
        out[((b*64 + o)*256 + f)*256 + tid] = r;
    }
}

// ---------------------------------------------------------------------------
// K5: emit new_cache = concat(kt[...,1:], f_out[...,1:]) at d_out + OUT0
// ---------------------------------------------------------------------------
__global__ void __launch_bounds__(256)
k_cacheout(float* __restrict__ out)
{
    int i = blockIdx.x*256 + threadIdx.x;
    if (i >= BB*32*FF*319) return;
    int j  = i % 319;
    int r  = i / 319;
    int f  = r % 256; r /= 256;
    int cc = r % 32;
    int b  = r / 32;
    float val;
    if (cc < 16) val = g_ktf[((b*16 + cc     )*256 + f)*320 + j + 1];
    else         val = g_fo [((b*16 + (cc-16))*256 + f)*320 + j + 1];
    out[OUT0 + i] = val;
}

// ---------------------------------------------------------------------------
extern "C" void kernel_launch(void* const* d_in, const int* in_sizes, int n_in,
                              void* d_out, int out_size)
{
    const float* inp    = (const float*)d_in[0];
    const float* cache  = (const float*)d_in[1];
    const float* fqkv_w = (const float*)d_in[2];
    const float* fqkv_g = (const float*)d_in[3];
    const float* fqkv_b = (const float*)d_in[4];
    const float* fqkv_m = (const float*)d_in[5];
    const float* fqkv_v = (const float*)d_in[6];
    const float* fqkv_a = (const float*)d_in[7];
    const float* tqk_w  = (const float*)d_in[8];
    const float* tqk_g  = (const float*)d_in[9];
    const float* tqk_b  = (const float*)d_in[10];
    const float* tqk_m  = (const float*)d_in[11];
    const float* tqk_v  = (const float*)d_in[12];
    const float* tqk_a  = (const float*)d_in[13];
    const float* proj_w = (const float*)d_in[14];
    const float* proj_g = (const float*)d_in[15];
    const float* proj_b = (const float*)d_in[16];
    const float* proj_m = (const float*)d_in[17];
    const float* proj_v = (const float*)d_in[18];
    const float* proj_a = (const float*)d_in[19];
    float* out = (float*)d_out;

    dim3 gbf(256, 4);
    k_conv<<<gbf, 256>>>(inp, fqkv_w, fqkv_g, fqkv_b, fqkv_m, fqkv_v, fqkv_a,
                              tqk_w,  tqk_g,  tqk_b,  tqk_m,  tqk_v,  tqk_a);
    k_cachecopy<<<(BB*DD*FF*TCC + 255)/256, 256>>>(cache);

    dim3 gt1(8, 8, 192);
    k_trans1<<<gt1, 256>>>();

    k_fattn<<<gbf, 256>>>();

    dim3 gt2(8, 8, 64);
    k_trans2<<<gt2, 256>>>();

    k_tscore<<<gbf, 256>>>();

    dim3 gz(320, 4);
    k_zred<<<gz, 256>>>();

    k_tout_proj<<<gbf, 256>>>(inp, proj_w, proj_g, proj_b, proj_m, proj_v, proj_a, out);

    k_cacheout<<<(BB*32*FF*319 + 255)/256, 256>>>(out);
}